// round 12
// baseline (speedup 1.0000x reference)
#include <cuda_runtime.h>
#include <cuda_bf16.h>
#include <cuda_fp16.h>
#include <cstdint>

#define H_ENC 512
#define H_DEC 256
#define VOCAB 8192
#define BATCH 128
#define NTOT  16384
#define LSEQ  13
#define KX    1280           // H_DEC + H_ENC (attended) + H_ENC (h)
#define G4    2048           // 4*H_ENC
#define BV    (BATCH*VOCAB)  // 1048576

#define KP_H  1536           // 3*512  (split-K' for K=512 operands)
#define KP_X  3840           // 3*1280 (split-K' for x)

#define NQO   (H_ENC + VOCAB)        // 8704: [Qh | logits] combined N
#define QL_SPLITS 2
#define GT_SPLITS 8
#define PSTRIDE (BATCH * NQO)        // per-split stride in g_qlP

// ---------------- device scratch (no cudaMalloc allowed) ----------------
__device__ __half g_Ph[NTOT * H_ENC];               // 16 MB fp16: nh @ W_att2^T + b_att
__device__ __half g_nhh[NTOT * H_ENC];              // 16 MB fp16 copy of nh (for k_att)
__device__ float g_c[BATCH * H_ENC];
__device__ float g_score[NTOT];                     // e_n = exp(score_n)
__device__ float g_bg[G4];                          // b_ih + b_hh, gate-interleaved
__device__ float g_qlP[QL_SPLITS * BATCH * NQO];    // [Qh | logits] split-K partials
__device__ float g_gatesP[GT_SPLITS * BATCH * G4];  // gate-interleaved partials
__device__ int   g_cnt[16];                         // per-N-tile arrival counters
// split-bf16 interleaved operands: [hi | hi | lo] along K'
__device__ __nv_bfloat16 g_hb [BATCH * KP_H];       // h
__device__ __nv_bfloat16 g_xb [BATCH * KP_X];       // x = [emb | attended | h]
__device__ __nv_bfloat16 g_nhb[NTOT * KP_H];        // node_hidden_states
// split-bf16 interleaved weights: [hi | lo | hi] along K'
__device__ __nv_bfloat16 g_Wab2[H_ENC * KP_H];      // W_att[:, 512:]  (P)
__device__ __nv_bfloat16 g_Wqo [NQO * KP_H];        // [W_att[:,:512] ; W_out]
__device__ __nv_bfloat16 g_Wgb [G4 * KP_X];         // gate-interleaved [W_ih | W_hh]

// ---------------- math helpers ----------------
__device__ __forceinline__ float fast_tanh(float x) {
    float e = __expf(2.0f * x), r;
    asm("rcp.approx.f32 %0, %1;" : "=f"(r) : "f"(e + 1.0f));
    return 1.0f - 2.0f * r;
}
__device__ __forceinline__ float fsigm(float x) {
    float e = __expf(-x), r;
    asm("rcp.approx.f32 %0, %1;" : "=f"(r) : "f"(e + 1.0f));
    return r;
}
__device__ __forceinline__ void split2(float v, __nv_bfloat16& hi, __nv_bfloat16& lo) {
    hi = __float2bfloat16(v);
    lo = __float2bfloat16(v - __bfloat162float(hi));
}
__device__ __forceinline__ uint32_t smem_u32(const void* p) {
    uint32_t a;
    asm("{ .reg .u64 t; cvta.to.shared.u64 t, %1; cvt.u32.u64 %0, t; }"
        : "=r"(a) : "l"(p));
    return a;
}
__device__ __forceinline__ void mma16816(float* d, const uint32_t* a, const uint32_t* b) {
    asm volatile(
        "mma.sync.aligned.m16n8k16.row.col.f32.bf16.bf16.f32 "
        "{%0,%1,%2,%3}, {%4,%5,%6,%7}, {%8,%9}, {%0,%1,%2,%3};"
        : "+f"(d[0]), "+f"(d[1]), "+f"(d[2]), "+f"(d[3])
        : "r"(a[0]), "r"(a[1]), "r"(a[2]), "r"(a[3]), "r"(b[0]), "r"(b[1]));
}
#define LDMX4(r0, r1, r2, r3, addr) \
    asm volatile("ldmatrix.sync.aligned.m8n8.x4.shared.b16 {%0,%1,%2,%3}, [%4];" \
        : "=r"(r0), "=r"(r1), "=r"(r2), "=r"(r3) : "r"(addr))
#define CP16(dst, src) \
    asm volatile("cp.async.cg.shared.global [%0], [%1], 16;" :: "r"(dst), "l"(src))
#define CP_COMMIT() asm volatile("cp.async.commit_group;" ::: "memory")
#define CP_WAIT(n)  asm volatile("cp.async.wait_group %0;" :: "n"(n) : "memory")

// ---------------- HMMA GEMM: C[M,N] = A'[M,K'] @ W'[N,K']^T (bf16->fp32) ------
// MODE 0: split-K — each z writes its own fp32 partial buffer (no bias).
// MODE 1: non-split fp16 out + bias (P precompute).
// MODE 2: split-K partials + per-tile last-block fused LSTM (gates GEMM).
#define BMM 128
#define BNN 128
#define BKC 32
#define SROWB 80                       // padded row: 40 bf16 = 80 bytes
#define BUFB  (128 * SROWB)            // 10240 bytes per stage buffer
#define WOFF  (3 * BUFB)               // Ws region offset
#define DSMEM (6 * BUFB)               // 61440 bytes

template<int MODE>
__global__ void __launch_bounds__(128) mma_gemm(
    const __nv_bfloat16* __restrict__ A, int lda,
    const __nv_bfloat16* __restrict__ W, int ldw,
    const float* __restrict__ bias,
    void* __restrict__ Cv, int ldc,
    int chunks, int strideZ)
{
    extern __shared__ char dsm[];
    const uint32_t sbase = smem_u32(dsm);

    const int tid = threadIdx.x;
    const int wid = tid >> 5, lane = tid & 31;
    const int wm = wid & 1, wn = wid >> 1;
    const int g = lane >> 2, t4 = lane & 3;

    const int rowBase = blockIdx.x * BMM, colBase = blockIdx.y * BNN;
    const long kBase = (long)blockIdx.z * chunks * BKC;
    float* C = (float*)Cv;
    if (MODE != 1) C += (size_t)blockIdx.z * strideZ;

    float acc[4][8][4];
#pragma unroll
    for (int i = 0; i < 4; i++)
#pragma unroll
        for (int j = 0; j < 8; j++)
#pragma unroll
            for (int v = 0; v < 4; v++) acc[i][j][v] = 0.0f;

    const int lrow = tid >> 2, lseg = tid & 3;
    const __nv_bfloat16* aSrc = A + (size_t)(rowBase + lrow) * lda + lseg * 8;
    const __nv_bfloat16* wSrc = W + (size_t)(colBase + lrow) * ldw + lseg * 8;
    const uint32_t aDst0 = sbase + lrow * SROWB + lseg * 16;
    const uint32_t wDst0 = sbase + WOFF + lrow * SROWB + lseg * 16;

    const int aFragRow = wm * 64 + (lane & 15);
    const uint32_t aFragB0 = sbase + aFragRow * SROWB + ((lane >> 4) << 4);
    const int bFragRow = wn * 64 + (((lane >> 4) << 3) | (lane & 7));
    const uint32_t bFragB0 = sbase + WOFF + bFragRow * SROWB + ((lane & 8) << 1);

    const int pre = (chunks < 2) ? chunks : 2;
    for (int i = 0; i < pre; i++) {
        const long k0 = kBase + (long)i * BKC;
#pragma unroll
        for (int p = 0; p < 4; p++) {
            CP16(aDst0 + i * BUFB + p * (32 * SROWB), (const void*)(aSrc + k0 + (size_t)p * 32 * lda));
            CP16(wDst0 + i * BUFB + p * (32 * SROWB), (const void*)(wSrc + k0 + (size_t)p * 32 * ldw));
        }
        CP_COMMIT();
    }

    for (int c = 0; c < chunks; ++c) {
        const int buf = c % 3;
        if (c + 2 < chunks) {
            const int nb = (c + 2) % 3;
            const long k0 = kBase + (long)(c + 2) * BKC;
#pragma unroll
            for (int p = 0; p < 4; p++) {
                CP16(aDst0 + nb * BUFB + p * (32 * SROWB), (const void*)(aSrc + k0 + (size_t)p * 32 * lda));
                CP16(wDst0 + nb * BUFB + p * (32 * SROWB), (const void*)(wSrc + k0 + (size_t)p * 32 * ldw));
            }
            CP_COMMIT();
            CP_WAIT(2);
        } else if (c + 1 < chunks) {
            CP_WAIT(1);
        } else {
            CP_WAIT(0);
        }
        __syncthreads();

#pragma unroll
        for (int ks = 0; ks < 2; ks++) {
            uint32_t af[4][4], bf[8][2];
#pragma unroll
            for (int mt = 0; mt < 4; mt++) {
                uint32_t addr = aFragB0 + buf * BUFB + mt * (16 * SROWB) + ks * 32;
                LDMX4(af[mt][0], af[mt][1], af[mt][2], af[mt][3], addr);
            }
#pragma unroll
            for (int nt = 0; nt < 4; nt++) {
                uint32_t addr = bFragB0 + buf * BUFB + nt * (16 * SROWB) + ks * 32;
                LDMX4(bf[2 * nt][0], bf[2 * nt][1], bf[2 * nt + 1][0], bf[2 * nt + 1][1], addr);
            }
#pragma unroll
            for (int mt = 0; mt < 4; mt++)
#pragma unroll
                for (int j = 0; j < 8; j++)
                    mma16816(acc[mt][j], af[mt], bf[j]);
        }
        __syncthreads();
    }

    const int row0 = rowBase + wm * 64;
    const int col0 = colBase + wn * 64;
#pragma unroll
    for (int mt = 0; mt < 4; mt++) {
#pragma unroll
        for (int j = 0; j < 8; j++) {
            const int r = row0 + mt * 16 + g;
            const int cc = col0 + j * 8 + 2 * t4;
            float2 v0 = make_float2(acc[mt][j][0], acc[mt][j][1]);
            float2 v1 = make_float2(acc[mt][j][2], acc[mt][j][3]);
            if (MODE == 1) {
                float2 bb = *(const float2*)(bias + cc);
                v0.x += bb.x; v0.y += bb.y;
                v1.x += bb.x; v1.y += bb.y;
                __half* Ch = (__half*)Cv;
                *(__half2*)(Ch + (size_t)r * ldc + cc) = __floats2half2_rn(v0.x, v0.y);
                *(__half2*)(Ch + (size_t)(r + 8) * ldc + cc) = __floats2half2_rn(v1.x, v1.y);
            } else {
                *(float2*)(C + (size_t)r * ldc + cc) = v0;
                *(float2*)(C + (size_t)(r + 8) * ldc + cc) = v1;
            }
        }
    }

    if (MODE == 2) {
        // last split-block for this N-tile reduces partials + runs the LSTM
        __threadfence();
        __syncthreads();
        __shared__ int s_old;
        if (tid == 0) s_old = atomicAdd(&g_cnt[blockIdx.y], 1);
        __syncthreads();
        if (s_old != GT_SPLITS - 1) return;
        __threadfence();

        const int jBase = colBase >> 2;           // 32 j-groups per tile
        for (int cc2 = tid; cc2 < 128 * 32; cc2 += 128) {
            const int m = cc2 >> 5, jj = cc2 & 31;
            const int j = jBase + jj;
            float4 gsum = make_float4(0.f, 0.f, 0.f, 0.f);
#pragma unroll
            for (int z = 0; z < GT_SPLITS; z++) {
                float4 p = *(const float4*)&g_gatesP[(size_t)z * (BATCH * G4) +
                                                     (size_t)m * G4 + colBase + 4 * jj];
                gsum.x += p.x; gsum.y += p.y; gsum.z += p.z; gsum.w += p.w;
            }
            float4 bb = *(const float4*)&g_bg[colBase + 4 * jj];
            float ig = gsum.x + bb.x, fg = gsum.y + bb.y;
            float gg = gsum.z + bb.z, og = gsum.w + bb.w;
            const int ci = m * H_ENC + j;
            float cv = fsigm(fg) * g_c[ci] + fsigm(ig) * fast_tanh(gg);
            g_c[ci] = cv;
            float h = fsigm(og) * fast_tanh(cv);
            __nv_bfloat16 hi, lo;
            split2(h, hi, lo);
            g_hb[m * KP_H + j] = hi; g_hb[m * KP_H + 512 + j] = hi; g_hb[m * KP_H + 1024 + j] = lo;
            g_xb[m * KP_X + 768 + j] = hi; g_xb[m * KP_X + 2048 + j] = hi; g_xb[m * KP_X + 3328 + j] = lo;
        }
        if (tid == 0) g_cnt[blockIdx.y] = 0;      // reset for next step / replay
    }
}

// ---------------- setup: convert weights + nh, init state, zero out[0] ---------
#define S0 (H_ENC * H_ENC)
#define S1 (G4 * KX)
#define S2 (VOCAB * H_ENC)
#define S3 (NTOT * H_ENC)
__global__ void __launch_bounds__(256) k_setup(
    const float* __restrict__ W_att, const float* __restrict__ W_ih,
    const float* __restrict__ W_hh, const float* __restrict__ W_out,
    const float* __restrict__ nh,
    const float* __restrict__ b_ih, const float* __restrict__ b_hh,
    const int* __restrict__ root, const int* __restrict__ labels,
    const float* __restrict__ emb, float* __restrict__ out0)
{
    const int total = S0 + S1 + S2 + S3;
    int gid = blockIdx.x * blockDim.x + threadIdx.x;
    if (gid < G4) {
        // gate-interleaved bias: nn = j*4+gate  <- original row n = gate*512+j
        int gate = gid & 3, j = gid >> 2;
        g_bg[gid] = b_ih[gate * 512 + j] + b_hh[gate * 512 + j];
    }
    if (gid < 16) g_cnt[gid] = 0;
    for (int i = gid; i < BV; i += gridDim.x * blockDim.x) out0[i] = 0.0f;

    if (gid < BATCH * H_ENC) {
        int b = gid >> 9, j = gid & 511;
        float h0 = nh[(size_t)root[b] * H_ENC + j];
        g_c[gid] = 0.0f;
        __nv_bfloat16 hi, lo;
        split2(h0, hi, lo);
        g_hb[b * KP_H + j] = hi; g_hb[b * KP_H + 512 + j] = hi; g_hb[b * KP_H + 1024 + j] = lo;
        g_xb[b * KP_X + 768 + j] = hi; g_xb[b * KP_X + 2048 + j] = hi; g_xb[b * KP_X + 3328 + j] = lo;
        if (gid < BATCH * H_DEC) {
            int be = gid >> 8, je = gid & 255;
            float e = emb[(size_t)labels[be] * H_DEC + je];
            split2(e, hi, lo);
            g_xb[be * KP_X + je] = hi; g_xb[be * KP_X + 1280 + je] = hi; g_xb[be * KP_X + 2560 + je] = lo;
        }
    }

    for (int idx = gid; idx < total; idx += gridDim.x * blockDim.x) {
        if (idx < S0) {
            int n = idx >> 9, k = idx & 511;
            __nv_bfloat16 hi, lo;
            split2(W_att[n * 1024 + k], hi, lo);       // W_att1 -> Wqo rows 0..511
            g_Wqo[(size_t)n * KP_H + k] = hi;
            g_Wqo[(size_t)n * KP_H + 512 + k] = lo;
            g_Wqo[(size_t)n * KP_H + 1024 + k] = hi;
            split2(W_att[n * 1024 + 512 + k], hi, lo); // W_att2 -> P weights
            g_Wab2[n * KP_H + k] = hi; g_Wab2[n * KP_H + 512 + k] = lo;
            g_Wab2[n * KP_H + 1024 + k] = hi;
        } else if (idx < S0 + S1) {
            int t = idx - S0;
            int n = t / KX, k = t - n * KX;             // original row n
            float v = (k < 768) ? W_ih[n * 768 + k] : W_hh[n * 512 + (k - 768)];
            int gate = n >> 9, j = n & 511;
            int nn = j * 4 + gate;                      // gate-interleaved row
            __nv_bfloat16 hi, lo;
            split2(v, hi, lo);
            g_Wgb[(size_t)nn * KP_X + k] = hi;
            g_Wgb[(size_t)nn * KP_X + 1280 + k] = lo;
            g_Wgb[(size_t)nn * KP_X + 2560 + k] = hi;
        } else if (idx < S0 + S1 + S2) {
            int t = idx - S0 - S1;
            int n = t >> 9, k = t & 511;
            __nv_bfloat16 hi, lo;
            split2(W_out[(size_t)n * 512 + k], hi, lo); // W_out -> Wqo rows 512..
            g_Wqo[(size_t)(512 + n) * KP_H + k] = hi;
            g_Wqo[(size_t)(512 + n) * KP_H + 512 + k] = lo;
            g_Wqo[(size_t)(512 + n) * KP_H + 1024 + k] = hi;
        } else {
            int t = idx - S0 - S1 - S2;
            int n = t >> 9, k = t & 511;
            float v = nh[(size_t)n * 512 + k];
            __nv_bfloat16 hi, lo;
            split2(v, hi, lo);
            g_nhb[(size_t)n * KP_H + k] = hi;
            g_nhb[(size_t)n * KP_H + 512 + k] = hi;
            g_nhb[(size_t)n * KP_H + 1024 + k] = lo;
            g_nhh[(size_t)n * 512 + k] = __float2half(v);
        }
    }
}

// ---------------- k_score: score(t) [512 blocks] + out(t-1) [128 blocks] -------
__global__ void __launch_bounds__(256) k_score(
    const int* __restrict__ root, const float* __restrict__ v_att,
    const float* __restrict__ b_out, const float* __restrict__ emb,
    float* __restrict__ slabPrev, int doScore, int doOut)
{
    const int tid = threadIdx.x;

    if (blockIdx.x < 512) {
        if (!doScore) return;
        const int b = blockIdx.x >> 2, slice = blockIdx.x & 3;
        const int lid = tid & 31, wid = tid >> 5;
        __shared__ float sQ[H_ENC], sV[H_ENC];

        const int s0 = root[b];
        const int s1 = (b == BATCH - 1) ? NTOT : root[b + 1];
        const int len = s1 - s0;
        const int a0 = s0 + (len * slice) / 4;
        const int a1 = s0 + (len * (slice + 1)) / 4;

        for (int j = tid; j < H_ENC; j += 256) {
            sQ[j] = g_qlP[(size_t)b * NQO + j] + g_qlP[PSTRIDE + (size_t)b * NQO + j];
            sV[j] = v_att[j];
        }
        __syncthreads();

        const float2* sQ2 = (const float2*)sQ;
        const float2* sV2 = (const float2*)sV;
        for (int n = a0 + wid; n < a1; n += 8) {
            const __half2* Pr2 = (const __half2*)(g_Ph + (size_t)n * H_ENC);
            float acc = 0.0f;
#pragma unroll
            for (int it = 0; it < 8; ++it) {
                int j = lid + it * 32;
                float2 p = __half22float2(Pr2[j]);
                float2 q = sQ2[j], vv = sV2[j];
                acc += vv.x * fast_tanh(p.x + q.x) + vv.y * fast_tanh(p.y + q.y);
            }
#pragma unroll
            for (int o = 16; o; o >>= 1) acc += __shfl_xor_sync(0xffffffffu, acc, o);
            if (lid == 0) g_score[n] = __expf(acc);
        }
    } else {
        if (!doOut) return;
        const int b = blockIdx.x - 512;
        float* row = slabPrev + (size_t)b * VOCAB;
        float best = -3.402823466e38f;
        int bi = VOCAB;
        for (int j = tid; j < VOCAB; j += 256) {
            float v = b_out[j]
                + g_qlP[(size_t)b * NQO + H_ENC + j]
                + g_qlP[PSTRIDE + (size_t)b * NQO + H_ENC + j];
            row[j] = v;
            if (v > best) { best = v; bi = j; }
        }
        __shared__ float sv[256];
        __shared__ int si[256];
        __shared__ int s_cur;
        sv[tid] = best; si[tid] = bi;
        __syncthreads();
        for (int s = 128; s; s >>= 1) {
            if (tid < s) {
                float v2 = sv[tid + s]; int i2 = si[tid + s];
                if (v2 > sv[tid] || (v2 == sv[tid] && i2 < si[tid])) { sv[tid] = v2; si[tid] = i2; }
            }
            __syncthreads();
        }
        if (tid == 0) s_cur = si[0];
        __syncthreads();
        float e = emb[(size_t)s_cur * H_DEC + tid];   // H_DEC == 256 == blockDim
        __nv_bfloat16 hi, lo;
        split2(e, hi, lo);
        g_xb[b * KP_X + tid] = hi; g_xb[b * KP_X + 1280 + tid] = hi; g_xb[b * KP_X + 2560 + tid] = lo;
    }
}

// ---------------- k_att: attended[b, chunk*128..+128) ; 512 blocks (fp16 nh) ---
__global__ void __launch_bounds__(256) k_att(const int* __restrict__ root)
{
    const int tid = threadIdx.x;
    const int b = blockIdx.x >> 2, chunk = blockIdx.x & 3;
    const int s0 = root[b];
    const int s1 = (b == BATCH - 1) ? NTOT : root[b + 1];

    __shared__ float szred[8];
    __shared__ float s_invz;
    __shared__ float2 sacc[256];

    float z = 0.0f;
    for (int n = s0 + tid; n < s1; n += 256) z += g_score[n];
#pragma unroll
    for (int o = 16; o; o >>= 1) z += __shfl_xor_sync(0xffffffffu, z, o);
    if ((tid & 31) == 0) szred[tid >> 5] = z;
    __syncthreads();
    if (tid == 0) {
        float zz = 0.0f;
        for (int w = 0; w < 8; w++) zz += szred[w];
        s_invz = 1.0f / zz;
    }

    // 64 column-pairs x 4-way n-parallel; fp16 nh halves the stream
    const int cpair = tid & 63;
    const int col2 = chunk * 128 + 2 * cpair;
    const int par = tid >> 6;
    float2 acc = make_float2(0.0f, 0.0f);
    for (int n = s0 + par; n < s1; n += 4) {
        float w = g_score[n];
        float2 f = __half22float2(*(const __half2*)(g_nhh + (size_t)n * H_ENC + col2));
        acc.x += w * f.x;
        acc.y += w * f.y;
    }
    sacc[tid] = acc;
    __syncthreads();
    if (tid < 64) {
        float2 a0 = sacc[tid], a1 = sacc[tid + 64];
        float2 a2 = sacc[tid + 128], a3 = sacc[tid + 192];
        float ax = (a0.x + a1.x + a2.x + a3.x) * s_invz;
        float ay = (a0.y + a1.y + a2.y + a3.y) * s_invz;
        __nv_bfloat16 hi, lo;
        split2(ax, hi, lo);
        g_xb[b * KP_X + 256 + col2] = hi;
        g_xb[b * KP_X + 1536 + col2] = hi;
        g_xb[b * KP_X + 2816 + col2] = lo;
        split2(ay, hi, lo);
        g_xb[b * KP_X + 257 + col2] = hi;
        g_xb[b * KP_X + 1537 + col2] = hi;
        g_xb[b * KP_X + 2817 + col2] = lo;
    }
}

// ---------------- launch ----------------
extern "C" void kernel_launch(void* const* d_in, const int* in_sizes, int n_in,
                              void* d_out, int out_size) {
    const float* nh    = (const float*)d_in[0];
    const int*   labels= (const int*)  d_in[1];
    const int*   root  = (const int*)  d_in[2];
    const float* emb   = (const float*)d_in[3];
    const float* W_att = (const float*)d_in[4];
    const float* b_att = (const float*)d_in[5];
    const float* v_att = (const float*)d_in[6];
    const float* W_ih  = (const float*)d_in[7];
    const float* W_hh  = (const float*)d_in[8];
    const float* b_ih  = (const float*)d_in[9];
    const float* b_hh  = (const float*)d_in[10];
    const float* W_out = (const float*)d_in[11];
    const float* b_out = (const float*)d_in[12];
    float* out = (float*)d_out;

    float *pQlP, *pGatesP;
    __half* pPh;
    __nv_bfloat16 *pHb, *pXb, *pNhb, *pWab2, *pWqo, *pWgb;
    cudaGetSymbolAddress((void**)&pPh, g_Ph);
    cudaGetSymbolAddress((void**)&pQlP, g_qlP);
    cudaGetSymbolAddress((void**)&pGatesP, g_gatesP);
    cudaGetSymbolAddress((void**)&pHb, g_hb);
    cudaGetSymbolAddress((void**)&pXb, g_xb);
    cudaGetSymbolAddress((void**)&pNhb, g_nhb);
    cudaGetSymbolAddress((void**)&pWab2, g_Wab2);
    cudaGetSymbolAddress((void**)&pWqo, g_Wqo);
    cudaGetSymbolAddress((void**)&pWgb, g_Wgb);

    cudaFuncSetAttribute(mma_gemm<0>, cudaFuncAttributeMaxDynamicSharedMemorySize, DSMEM);
    cudaFuncSetAttribute(mma_gemm<1>, cudaFuncAttributeMaxDynamicSharedMemorySize, DSMEM);
    cudaFuncSetAttribute(mma_gemm<2>, cudaFuncAttributeMaxDynamicSharedMemorySize, DSMEM);

    // ---- setup (launch #4 = first k_score -> ncu -s 5 lands on it)
    k_setup<<<2048, 256>>>(W_att, W_ih, W_hh, W_out, nh, b_ih, b_hh,
                           root, labels, emb, out);
    // P(fp16) = nh @ W_att[:,512:]^T + b_att
    mma_gemm<1><<<dim3(NTOT / 128, H_ENC / 128, 1), 128, DSMEM>>>(
        pNhb, KP_H, pWab2, KP_H, b_att, pPh, H_ENC, KP_H / BKC, 0);
    // bootstrap [Qh1 | junk logits] partials = h0 @ Wqo^T (split-2)
    mma_gemm<0><<<dim3(1, NQO / 128, QL_SPLITS), 128, DSMEM>>>(
        pHb, KP_H, pWqo, KP_H, nullptr, pQlP, NQO,
        KP_H / BKC / QL_SPLITS, PSTRIDE);

    // ---- decode: [score|out] -> att -> gates(+lstm) -> ql GEMM ----
    for (int t = 1; t < LSEQ; t++) {
        float* slabPrev = (t > 1) ? (out + (size_t)(t - 1) * BV) : nullptr;
        k_score<<<640, 256>>>(root, v_att, b_out, emb, slabPrev, 1, t > 1);
        k_att<<<512, 256>>>(root);
        // gates partials (split-8) + fused LSTM in last block per N-tile
        mma_gemm<2><<<dim3(1, G4 / 128, GT_SPLITS), 128, DSMEM>>>(
            pXb, KP_X, pWgb, KP_X, nullptr, pGatesP, G4,
            KP_X / BKC / GT_SPLITS, BATCH * G4);
        // [Qh_{t+1} | logits_t] partials = h @ Wqo^T (split-2)
        mma_gemm<0><<<dim3(1, NQO / 128, QL_SPLITS), 128, DSMEM>>>(
            pHb, KP_H, pWqo, KP_H, nullptr, pQlP, NQO,
            KP_H / BKC / QL_SPLITS, PSTRIDE);
    }
    // final out for step 12
    k_score<<<640, 256>>>(root, v_att, b_out, emb,
                          out + (size_t)(LSEQ - 1) * BV, 0, 1);
}

// round 15
// speedup vs baseline: 1.3506x; 1.3506x over previous
#include <cuda_runtime.h>
#include <cuda_bf16.h>
#include <cuda_fp16.h>
#include <cstdint>

#define H_ENC 512
#define H_DEC 256
#define VOCAB 8192
#define BATCH 128
#define NTOT  16384
#define LSEQ  13
#define KX    1280
#define G4    2048
#define BV    (BATCH*VOCAB)

#define KP_H  1536
#define KP_X  3840

#define NQO   (H_ENC + VOCAB)
#define QL_SPLITS 2
#define GT_SPLITS 8
#define PSTRIDE (BATCH * NQO)

// ---------------- device scratch ----------------
__device__ __nv_bfloat16 d_hb [BATCH * KP_H];       // h, split-bf16 [hi|hi|lo]
__device__ __nv_bfloat16 d_xb [BATCH * KP_X];       // x = [emb|attended|h]
__device__ __nv_bfloat16 d_nhb[NTOT * KP_H];        // node hidden, split-bf16
__device__ __nv_bfloat16 d_Wab2[H_ENC * KP_H];      // W_att[:,512:] [hi|lo|hi]
__device__ __nv_bfloat16 d_Wqo [NQO * KP_H];        // [W_att[:,:512] ; W_out]
__device__ __nv_bfloat16 d_Wgb [G4 * KP_X];         // [W_ih | W_hh]
__device__ __half dPh [NTOT * H_ENC];               // fp16 P = nh@Wa2^T + b_att
__device__ __half dNhh[NTOT * H_ENC];               // fp16 nh copy (att pass)
__device__ float dC   [BATCH * H_ENC];
__device__ float dE   [NTOT];                       // e_n = exp(score_n)
__device__ float dBg  [G4];
__device__ float dQlP [QL_SPLITS * BATCH * NQO];
__device__ float dGtP [GT_SPLITS * BATCH * G4];

// ---------------- helpers ----------------
__device__ __forceinline__ float ftanh_v2(float x) {
    float e = __expf(2.0f * x), r;
    asm("rcp.approx.f32 %0, %1;" : "=f"(r) : "f"(e + 1.0f));
    return 1.0f - 2.0f * r;
}
__device__ __forceinline__ float fsigm_v2(float x) {
    float e = __expf(-x), r;
    asm("rcp.approx.f32 %0, %1;" : "=f"(r) : "f"(e + 1.0f));
    return r;
}
__device__ __forceinline__ void bsplit(float v, __nv_bfloat16& hi, __nv_bfloat16& lo) {
    hi = __float2bfloat16(v);
    lo = __float2bfloat16(v - __bfloat162float(hi));
}
__device__ __forceinline__ uint32_t s2u32(const void* p) {
    uint32_t a;
    asm("{ .reg .u64 t; cvta.to.shared.u64 t, %1; cvt.u32.u64 %0, t; }"
        : "=r"(a) : "l"(p));
    return a;
}
__device__ __forceinline__ void hmma(float* d, const uint32_t* a, const uint32_t* b) {
    asm volatile(
        "mma.sync.aligned.m16n8k16.row.col.f32.bf16.bf16.f32 "
        "{%0,%1,%2,%3}, {%4,%5,%6,%7}, {%8,%9}, {%0,%1,%2,%3};"
        : "+f"(d[0]), "+f"(d[1]), "+f"(d[2]), "+f"(d[3])
        : "r"(a[0]), "r"(a[1]), "r"(a[2]), "r"(a[3]), "r"(b[0]), "r"(b[1]));
}
#define LDM4(r0, r1, r2, r3, addr) \
    asm volatile("ldmatrix.sync.aligned.m8n8.x4.shared.b16 {%0,%1,%2,%3}, [%4];" \
        : "=r"(r0), "=r"(r1), "=r"(r2), "=r"(r3) : "r"(addr))
#define CPA16(dst, src) \
    asm volatile("cp.async.cg.shared.global [%0], [%1], 16;" :: "r"(dst), "l"(src))
#define CPA_COMMIT() asm volatile("cp.async.commit_group;" ::: "memory")
#define CPA_WAIT(n)  asm volatile("cp.async.wait_group %0;" :: "n"(n) : "memory")

// ---------------- HMMA GEMM (3-stage cp.async, ldmatrix, 128x128 tile) --------
// MODE 0: split-K fp32 partials. MODE 1: non-split fp16 out + bias.
#define BKC 32
#define SROWB 80
#define BUFB  (128 * SROWB)
#define WOFF  (3 * BUFB)
#define DSMEM (6 * BUFB)

template<int MODE>
__global__ void __launch_bounds__(128) gemm_v2(
    const __nv_bfloat16* __restrict__ A, int lda,
    const __nv_bfloat16* __restrict__ W, int ldw,
    const float* __restrict__ bias,
    void* __restrict__ Cv, int ldc,
    int chunks, int strideZ)
{
    extern __shared__ char dsm[];
    const uint32_t sbase = s2u32(dsm);

    const int tid = threadIdx.x;
    const int wid = tid >> 5, lane = tid & 31;
    const int wm = wid & 1, wn = wid >> 1;
    const int g = lane >> 2, t4 = lane & 3;

    const int rowBase = blockIdx.x * 128, colBase = blockIdx.y * 128;
    const long kBase = (long)blockIdx.z * chunks * BKC;
    float* C = (float*)Cv;
    if (MODE == 0) C += (size_t)blockIdx.z * strideZ;

    float acc[4][8][4];
#pragma unroll
    for (int i = 0; i < 4; i++)
#pragma unroll
        for (int j = 0; j < 8; j++)
#pragma unroll
            for (int v = 0; v < 4; v++) acc[i][j][v] = 0.0f;

    const int lrow = tid >> 2, lseg = tid & 3;
    const __nv_bfloat16* aSrc = A + (size_t)(rowBase + lrow) * lda + lseg * 8;
    const __nv_bfloat16* wSrc = W + (size_t)(colBase + lrow) * ldw + lseg * 8;
    const uint32_t aDst0 = sbase + lrow * SROWB + lseg * 16;
    const uint32_t wDst0 = sbase + WOFF + lrow * SROWB + lseg * 16;

    const int aFragRow = wm * 64 + (lane & 15);
    const uint32_t aFragB0 = sbase + aFragRow * SROWB + ((lane >> 4) << 4);
    const int bFragRow = wn * 64 + (((lane >> 4) << 3) | (lane & 7));
    const uint32_t bFragB0 = sbase + WOFF + bFragRow * SROWB + ((lane & 8) << 1);

    const int pre = (chunks < 2) ? chunks : 2;
    for (int i = 0; i < pre; i++) {
        const long k0 = kBase + (long)i * BKC;
#pragma unroll
        for (int p = 0; p < 4; p++) {
            CPA16(aDst0 + i * BUFB + p * (32 * SROWB), (const void*)(aSrc + k0 + (size_t)p * 32 * lda));
            CPA16(wDst0 + i * BUFB + p * (32 * SROWB), (const void*)(wSrc + k0 + (size_t)p * 32 * ldw));
        }
        CPA_COMMIT();
    }

    for (int c = 0; c < chunks; ++c) {
        const int buf = c % 3;
        if (c + 2 < chunks) {
            const int nb = (c + 2) % 3;
            const long k0 = kBase + (long)(c + 2) * BKC;
#pragma unroll
            for (int p = 0; p < 4; p++) {
                CPA16(aDst0 + nb * BUFB + p * (32 * SROWB), (const void*)(aSrc + k0 + (size_t)p * 32 * lda));
                CPA16(wDst0 + nb * BUFB + p * (32 * SROWB), (const void*)(wSrc + k0 + (size_t)p * 32 * ldw));
            }
            CPA_COMMIT();
            CPA_WAIT(2);
        } else if (c + 1 < chunks) {
            CPA_WAIT(1);
        } else {
            CPA_WAIT(0);
        }
        __syncthreads();

#pragma unroll
        for (int ks = 0; ks < 2; ks++) {
            uint32_t af[4][4], bf[8][2];
#pragma unroll
            for (int mt = 0; mt < 4; mt++) {
                uint32_t addr = aFragB0 + buf * BUFB + mt * (16 * SROWB) + ks * 32;
                LDM4(af[mt][0], af[mt][1], af[mt][2], af[mt][3], addr);
            }
#pragma unroll
            for (int nt = 0; nt < 4; nt++) {
                uint32_t addr = bFragB0 + buf * BUFB + nt * (16 * SROWB) + ks * 32;
                LDM4(bf[2 * nt][0], bf[2 * nt][1], bf[2 * nt + 1][0], bf[2 * nt + 1][1], addr);
            }
#pragma unroll
            for (int mt = 0; mt < 4; mt++)
#pragma unroll
                for (int j = 0; j < 8; j++)
                    hmma(acc[mt][j], af[mt], bf[j]);
        }
        __syncthreads();
    }

    const int row0 = rowBase + wm * 64;
    const int col0 = colBase + wn * 64;
#pragma unroll
    for (int mt = 0; mt < 4; mt++) {
#pragma unroll
        for (int j = 0; j < 8; j++) {
            const int r = row0 + mt * 16 + g;
            const int cc = col0 + j * 8 + 2 * t4;
            float2 v0 = make_float2(acc[mt][j][0], acc[mt][j][1]);
            float2 v1 = make_float2(acc[mt][j][2], acc[mt][j][3]);
            if (MODE == 1) {
                float2 bb = *(const float2*)(bias + cc);
                v0.x += bb.x; v0.y += bb.y;
                v1.x += bb.x; v1.y += bb.y;
                __half* Ch = (__half*)Cv;
                *(__half2*)(Ch + (size_t)r * ldc + cc) = __floats2half2_rn(v0.x, v0.y);
                *(__half2*)(Ch + (size_t)(r + 8) * ldc + cc) = __floats2half2_rn(v1.x, v1.y);
            } else {
                *(float2*)(C + (size_t)r * ldc + cc) = v0;
                *(float2*)(C + (size_t)(r + 8) * ldc + cc) = v1;
            }
        }
    }
}

// ---------------- setup ----------------
#define S0 (H_ENC * H_ENC)
#define S1 (G4 * KX)
#define S2 (VOCAB * H_ENC)
#define S3 (NTOT * H_ENC)
__global__ void __launch_bounds__(256) prep_v2(
    const float* __restrict__ W_att, const float* __restrict__ W_ih,
    const float* __restrict__ W_hh, const float* __restrict__ W_out,
    const float* __restrict__ nh,
    const float* __restrict__ b_ih, const float* __restrict__ b_hh,
    const int* __restrict__ root, const int* __restrict__ labels,
    const float* __restrict__ emb, float* __restrict__ out0)
{
    const int total = S0 + S1 + S2 + S3;
    int gid = blockIdx.x * blockDim.x + threadIdx.x;
    if (gid < G4) dBg[gid] = b_ih[gid] + b_hh[gid];
    for (int i = gid; i < BV; i += gridDim.x * blockDim.x) out0[i] = 0.0f;

    if (gid < BATCH * H_ENC) {
        int b = gid >> 9, j = gid & 511;
        float h0 = nh[(size_t)root[b] * H_ENC + j];
        dC[gid] = 0.0f;
        __nv_bfloat16 hi, lo;
        bsplit(h0, hi, lo);
        d_hb[b * KP_H + j] = hi; d_hb[b * KP_H + 512 + j] = hi; d_hb[b * KP_H + 1024 + j] = lo;
        d_xb[b * KP_X + 768 + j] = hi; d_xb[b * KP_X + 2048 + j] = hi; d_xb[b * KP_X + 3328 + j] = lo;
        if (gid < BATCH * H_DEC) {
            int be = gid >> 8, je = gid & 255;
            float e = emb[(size_t)labels[be] * H_DEC + je];
            bsplit(e, hi, lo);
            d_xb[be * KP_X + je] = hi; d_xb[be * KP_X + 1280 + je] = hi; d_xb[be * KP_X + 2560 + je] = lo;
        }
    }

    for (int idx = gid; idx < total; idx += gridDim.x * blockDim.x) {
        if (idx < S0) {
            int n = idx >> 9, k = idx & 511;
            __nv_bfloat16 hi, lo;
            bsplit(W_att[n * 1024 + k], hi, lo);
            d_Wqo[(size_t)n * KP_H + k] = hi;
            d_Wqo[(size_t)n * KP_H + 512 + k] = lo;
            d_Wqo[(size_t)n * KP_H + 1024 + k] = hi;
            bsplit(W_att[n * 1024 + 512 + k], hi, lo);
            d_Wab2[n * KP_H + k] = hi; d_Wab2[n * KP_H + 512 + k] = lo;
            d_Wab2[n * KP_H + 1024 + k] = hi;
        } else if (idx < S0 + S1) {
            int t = idx - S0;
            int n = t / KX, k = t - n * KX;
            float v = (k < 768) ? W_ih[n * 768 + k] : W_hh[n * 512 + (k - 768)];
            __nv_bfloat16 hi, lo;
            bsplit(v, hi, lo);
            d_Wgb[(size_t)n * KP_X + k] = hi;
            d_Wgb[(size_t)n * KP_X + 1280 + k] = lo;
            d_Wgb[(size_t)n * KP_X + 2560 + k] = hi;
        } else if (idx < S0 + S1 + S2) {
            int t = idx - S0 - S1;
            int n = t >> 9, k = t & 511;
            __nv_bfloat16 hi, lo;
            bsplit(W_out[(size_t)n * 512 + k], hi, lo);
            d_Wqo[(size_t)(512 + n) * KP_H + k] = hi;
            d_Wqo[(size_t)(512 + n) * KP_H + 512 + k] = lo;
            d_Wqo[(size_t)(512 + n) * KP_H + 1024 + k] = hi;
        } else {
            int t = idx - S0 - S1 - S2;
            int n = t >> 9, k = t & 511;
            float v = nh[(size_t)n * 512 + k];
            __nv_bfloat16 hi, lo;
            bsplit(v, hi, lo);
            d_nhb[(size_t)n * KP_H + k] = hi;
            d_nhb[(size_t)n * KP_H + 512 + k] = hi;
            d_nhb[(size_t)n * KP_H + 1024 + k] = lo;
            dNhh[(size_t)n * 512 + k] = __float2half(v);
        }
    }
}

// ---------------- scores: e_n = exp(v . tanh(P_n + Qh_b)); fp16 P --------------
__global__ void __launch_bounds__(256) scor_v2(
    const int* __restrict__ root, const float* __restrict__ v_att)
{
    const int b = blockIdx.x >> 2, slice = blockIdx.x & 3;
    const int tid = threadIdx.x, lid = tid & 31, wid = tid >> 5;
    __shared__ float sQ[H_ENC], sV[H_ENC];

    const int s0 = root[b];
    const int s1 = (b == BATCH - 1) ? NTOT : root[b + 1];
    const int len = s1 - s0;
    const int a0 = s0 + (len * slice) / 4;
    const int a1 = s0 + (len * (slice + 1)) / 4;

    for (int j = tid; j < H_ENC; j += 256) {
        sQ[j] = dQlP[(size_t)b * NQO + j] + dQlP[PSTRIDE + (size_t)b * NQO + j];
        sV[j] = v_att[j];
    }
    __syncthreads();

    const float2* sQ2 = (const float2*)sQ;
    const float2* sV2 = (const float2*)sV;
    for (int n = a0 + wid; n < a1; n += 8) {
        const __half2* Pr2 = (const __half2*)(dPh + (size_t)n * H_ENC);
        float acc = 0.0f;
#pragma unroll
        for (int it = 0; it < 8; ++it) {
            int j = lid + it * 32;
            float2 p = __half22float2(Pr2[j]);
            float2 q = sQ2[j], vv = sV2[j];
            acc += vv.x * ftanh_v2(p.x + q.x) + vv.y * ftanh_v2(p.y + q.y);
        }
#pragma unroll
        for (int o = 16; o; o >>= 1) acc += __shfl_xor_sync(0xffffffffu, acc, o);
        if (lid == 0) dE[n] = __expf(acc);
    }
}

// ---------------- attended (512 blocks, fp16 nh) + out/argmax (128 blocks) -----
__global__ void __launch_bounds__(256) attn_v2(
    const int* __restrict__ root,
    const float* __restrict__ b_out, const float* __restrict__ emb,
    float* __restrict__ slabPrev, int doAtt, int doOut)
{
    const int tid = threadIdx.x;

    if (blockIdx.x < 512) {
        if (!doAtt) return;
        const int b = blockIdx.x >> 2, chunk = blockIdx.x & 3;
        const int s0 = root[b];
        const int s1 = (b == BATCH - 1) ? NTOT : root[b + 1];

        __shared__ float szred[8];
        __shared__ float s_invz;
        __shared__ float2 sacc[256];

        float z = 0.0f;
        for (int n = s0 + tid; n < s1; n += 256) z += dE[n];
#pragma unroll
        for (int o = 16; o; o >>= 1) z += __shfl_xor_sync(0xffffffffu, z, o);
        if ((tid & 31) == 0) szred[tid >> 5] = z;
        __syncthreads();
        if (tid == 0) {
            float zz = 0.0f;
            for (int w = 0; w < 8; w++) zz += szred[w];
            s_invz = 1.0f / zz;
        }

        const int cpair = tid & 63;
        const int col2 = chunk * 128 + 2 * cpair;
        const int par = tid >> 6;
        float2 acc = make_float2(0.0f, 0.0f);
        for (int n = s0 + par; n < s1; n += 4) {
            float w = dE[n];
            float2 f = __half22float2(*(const __half2*)(dNhh + (size_t)n * H_ENC + col2));
            acc.x += w * f.x;
            acc.y += w * f.y;
        }
        sacc[tid] = acc;
        __syncthreads();
        if (tid < 64) {
            float2 a0 = sacc[tid], a1 = sacc[tid + 64];
            float2 a2 = sacc[tid + 128], a3 = sacc[tid + 192];
            float ax = (a0.x + a1.x + a2.x + a3.x) * s_invz;
            float ay = (a0.y + a1.y + a2.y + a3.y) * s_invz;
            __nv_bfloat16 hi, lo;
            bsplit(ax, hi, lo);
            d_xb[b * KP_X + 256 + col2] = hi;
            d_xb[b * KP_X + 1536 + col2] = hi;
            d_xb[b * KP_X + 2816 + col2] = lo;
            bsplit(ay, hi, lo);
            d_xb[b * KP_X + 257 + col2] = hi;
            d_xb[b * KP_X + 1537 + col2] = hi;
            d_xb[b * KP_X + 2817 + col2] = lo;
        }
    } else {
        if (!doOut) return;
        const int b = blockIdx.x - 512;
        float* row = slabPrev + (size_t)b * VOCAB;
        float best = -3.402823466e38f;
        int bi = VOCAB;
        for (int j = tid; j < VOCAB; j += 256) {
            float v = b_out[j]
                + dQlP[(size_t)b * NQO + H_ENC + j]
                + dQlP[PSTRIDE + (size_t)b * NQO + H_ENC + j];
            row[j] = v;
            if (v > best) { best = v; bi = j; }
        }
        __shared__ float sv[256];
        __shared__ int si[256];
        __shared__ int s_cur;
        sv[tid] = best; si[tid] = bi;
        __syncthreads();
        for (int s = 128; s; s >>= 1) {
            if (tid < s) {
                float v2 = sv[tid + s]; int i2 = si[tid + s];
                if (v2 > sv[tid] || (v2 == sv[tid] && i2 < si[tid])) { sv[tid] = v2; si[tid] = i2; }
            }
            __syncthreads();
        }
        if (tid == 0) s_cur = si[0];
        __syncthreads();
        float e = emb[(size_t)s_cur * H_DEC + tid];
        __nv_bfloat16 hi, lo;
        bsplit(e, hi, lo);
        d_xb[b * KP_X + tid] = hi; d_xb[b * KP_X + 1280 + tid] = hi; d_xb[b * KP_X + 2560 + tid] = lo;
    }
}

// ---------------- gate reduce + bias + LSTM update ----------------
__global__ void __launch_bounds__(256) cell_v2() {
    const int idx = blockIdx.x * blockDim.x + threadIdx.x;
    const int b = idx >> 9, j = idx & 511;
    float ig = dBg[j], fg = dBg[512 + j], gg = dBg[1024 + j], og = dBg[1536 + j];
#pragma unroll
    for (int z = 0; z < GT_SPLITS; z++) {
        const float* gr = dGtP + (size_t)z * (BATCH * G4) + b * G4 + j;
        ig += gr[0]; fg += gr[512]; gg += gr[1024]; og += gr[1536];
    }
    float c = fsigm_v2(fg) * dC[idx] + fsigm_v2(ig) * ftanh_v2(gg);
    dC[idx] = c;
    float h = fsigm_v2(og) * ftanh_v2(c);
    __nv_bfloat16 hi, lo;
    bsplit(h, hi, lo);
    d_hb[b * KP_H + j] = hi; d_hb[b * KP_H + 512 + j] = hi; d_hb[b * KP_H + 1024 + j] = lo;
    d_xb[b * KP_X + 768 + j] = hi; d_xb[b * KP_X + 2048 + j] = hi; d_xb[b * KP_X + 3328 + j] = lo;
}

// ---------------- launch ----------------
extern "C" void kernel_launch(void* const* d_in, const int* in_sizes, int n_in,
                              void* d_out, int out_size) {
    const float* nh    = (const float*)d_in[0];
    const int*   labels= (const int*)  d_in[1];
    const int*   root  = (const int*)  d_in[2];
    const float* emb   = (const float*)d_in[3];
    const float* W_att = (const float*)d_in[4];
    const float* b_att = (const float*)d_in[5];
    const float* v_att = (const float*)d_in[6];
    const float* W_ih  = (const float*)d_in[7];
    const float* W_hh  = (const float*)d_in[8];
    const float* b_ih  = (const float*)d_in[9];
    const float* b_hh  = (const float*)d_in[10];
    const float* W_out = (const float*)d_in[11];
    const float* b_out = (const float*)d_in[12];
    float* out = (float*)d_out;

    float *pQlP, *pGtP;
    __half* pPh;
    __nv_bfloat16 *pHb, *pXb, *pNhb, *pWab2, *pWqo, *pWgb;
    cudaGetSymbolAddress((void**)&pPh, dPh);
    cudaGetSymbolAddress((void**)&pQlP, dQlP);
    cudaGetSymbolAddress((void**)&pGtP, dGtP);
    cudaGetSymbolAddress((void**)&pHb, d_hb);
    cudaGetSymbolAddress((void**)&pXb, d_xb);
    cudaGetSymbolAddress((void**)&pNhb, d_nhb);
    cudaGetSymbolAddress((void**)&pWab2, d_Wab2);
    cudaGetSymbolAddress((void**)&pWqo, d_Wqo);
    cudaGetSymbolAddress((void**)&pWgb, d_Wgb);

    cudaFuncSetAttribute(gemm_v2<0>, cudaFuncAttributeMaxDynamicSharedMemorySize, DSMEM);
    cudaFuncSetAttribute(gemm_v2<1>, cudaFuncAttributeMaxDynamicSharedMemorySize, DSMEM);

    prep_v2<<<2048, 256>>>(W_att, W_ih, W_hh, W_out, nh, b_ih, b_hh,
                           root, labels, emb, out);
    // P(fp16) = nh @ W_att[:,512:]^T + b_att
    gemm_v2<1><<<dim3(NTOT / 128, H_ENC / 128, 1), 128, DSMEM>>>(
        pNhb, KP_H, pWab2, KP_H, b_att, pPh, H_ENC, KP_H / BKC, 0);
    // bootstrap [Qh1 | unused] partials = h0 @ Wqo^T (split-2)
    gemm_v2<0><<<dim3(1, NQO / 128, QL_SPLITS), 128, DSMEM>>>(
        pHb, KP_H, pWqo, KP_H, nullptr, pQlP, NQO,
        KP_H / BKC / QL_SPLITS, PSTRIDE);

    for (int t = 1; t < LSEQ; t++) {
        float* slabPrev = (t > 1) ? (out + (size_t)(t - 1) * BV) : nullptr;
        scor_v2<<<512, 256>>>(root, v_att);
        attn_v2<<<640, 256>>>(root, b_out, emb, slabPrev, 1, t > 1);
        gemm_v2<0><<<dim3(1, G4 / 128, GT_SPLITS), 128, DSMEM>>>(
            pXb, KP_X, pWgb, KP_X, nullptr, pGtP, G4,
            KP_X / BKC / GT_SPLITS, BATCH * G4);
        cell_v2<<<256, 256>>>();
        gemm_v2<0><<<dim3(1, NQO / 128, QL_SPLITS), 128, DSMEM>>>(
            pHb, KP_H, pWqo, KP_H, nullptr, pQlP, NQO,
            KP_H / BKC / QL_SPLITS, PSTRIDE);
    }
    attn_v2<<<640, 256>>>(root, b_out, emb,
                          out + (size_t)(LSEQ - 1) * BV, 0, 1);
}